// round 13
// baseline (speedup 1.0000x reference)
#include <cuda_runtime.h>
#include <math.h>

#define MESH  129
#define NB    4
#define NP    512
#define BP    2048
#define KOFF  64
#define HALF  8321               // modes idx <= center; rest via Hermitian symmetry
#define TROWS 65
#define TN    (TROWS*MESH)       // 8385
#define PC    8                  // p-chunks in k_T
#define PPTS  (NP/PC)            // 64 points per k_T block
#define TI    18                 // k_T i-tile rows
#define TJ    26                 // k_T j-tile cols
#define ITILES 4
#define JTILES 5
#define NTHR_T 117               // 13 x 9
#define PTS   16                 // points per k_energy block (8 packed pairs)
#define NTHR_E 512               // k_energy threads (16 warps, 1 block/SM)

typedef unsigned long long u64;

// ---- f32x2 packed helpers ----
__device__ __forceinline__ u64 fma2(u64 a, u64 b, u64 c) {
    u64 d; asm("fma.rn.f32x2 %0, %1, %2, %3;" : "=l"(d) : "l"(a), "l"(b), "l"(c)); return d;
}
__device__ __forceinline__ u64 mul2(u64 a, u64 b) {
    u64 d; asm("mul.rn.f32x2 %0, %1, %2;" : "=l"(d) : "l"(a), "l"(b)); return d;
}
__device__ __forceinline__ u64 pack2(float lo, float hi) {
    u64 d; asm("mov.b64 %0, {%1, %2};" : "=l"(d) : "r"(__float_as_uint(lo)), "r"(__float_as_uint(hi))); return d;
}
__device__ __forceinline__ void unpack2(u64 v, float& lo, float& hi) {
    unsigned a, b; asm("mov.b64 {%0, %1}, %2;" : "=r"(a), "=r"(b) : "l"(v));
    lo = __uint_as_float(a); hi = __uint_as_float(b);
}

// Scratch (__device__ globals; no allocation allowed)
__device__ float2 g_Tp[PC*NB*TN];
__device__ float4 g_TW[NB*TN];
__device__ int    g_cntT[NB*ITILES*JTILES];

// ---- constants ----
#define TAUF   ((float)(12.0 / (129.0 * 129.0)))
#define T258   (258.0f * TAUF)
#define KC     6.144212353e-6f          /* e^{-129^2 * tau} = e^{-12} */
#define INV2PI 0.15915494309189535f
#define PI2_HI 6.28318548202514648f
#define PI2_LO (-1.74845553e-7f)

// cos/sin of (m*xx) with exact-product + Cody-Waite 2pi reduction
__device__ __forceinline__ float2 sincos_red(float m, float xx)
{
    float ph = m * xx;
    float pl = fmaf(m, xx, -ph);
    float n  = rintf(ph * INV2PI);
    float r  = fmaf(n, -PI2_HI, ph);
    r = fmaf(n, -PI2_LO, r);
    r += pl;
    float s, c;
    __sincosf(r, &s, &c);
    return make_float2(c, s);
}

// Fast closed-form 1D DFT of periodic spread Gaussian.
__device__ __forceinline__ float2 eval_fast(float kk, float xx, float rc, float rs)
{
    const float Cst = 129.0f * sqrtf(12.566370614f * TAUF) * INV2PI;
    float E  = __expf(-TAUF * kk * kk) * Cst;
    float D  = __expf(-T258 * kk);
    float Di = __fdividef(1.0f, D);
    float ep = D * KC, em = Di * KC;
    float2 cs = sincos_red(kk, xx);
    float bc = cs.x, bs = -cs.y;                  // base = e^{-i kk x}
    float tpre = fmaf(bc, rc,  bs * rs);
    float tpim = fmaf(bs, rc, -bc * rs);
    float tmre = fmaf(bc, rc, -bs * rs);
    float tmim = fmaf(bc, rs,  bs * rc);
    float re = fmaf(ep, tpre, fmaf(em, tmre, bc));
    float im = fmaf(ep, tpim, fmaf(em, tmim, bs));
    return make_float2(E * re, E * im);
}

// ---------------------------------------------------------------------------
// Kernel A: partial T[pc,b,i,j] = sum_p A[p,i]*B[p,j]; 18x26 tiles, 117 thr.
// Grid 5x4x32 = 640 blocks (~4.3/SM). Tail block fuses partials + weights.
// (Identical to R11.)
// ---------------------------------------------------------------------------
__global__ void __launch_bounds__(NTHR_T) k_T(
    const float* __restrict__ x,
    const float* __restrict__ s0, const float* __restrict__ s1,
    const float* __restrict__ a0, const float* __restrict__ a1)
{
    __shared__ float sAx[PPTS][TI];
    __shared__ float sAy[PPTS][TI];
    __shared__ float sBx[PPTS][TJ];
    __shared__ float sBy[PPTS][TJ];
    __shared__ float sxp[PPTS][2];
    __shared__ float srot[PPTS][2][2];
    __shared__ int s_ticket;

    int b  = blockIdx.z & 3;
    int pc = blockIdx.z >> 2;
    int i0 = blockIdx.y * TI;
    int j0 = blockIdx.x * TJ;
    int tid = threadIdx.x;
    int tx = tid % 13, ty = tid / 13;

    const int pbase = b * NP + pc * PPTS;

    for (int l = tid; l < PPTS * 2; l += NTHR_T)
        sxp[l >> 1][l & 1] = x[(pbase + (l >> 1)) * 2 + (l & 1)];
    __syncthreads();
    for (int l = tid; l < PPTS * 2; l += NTHR_T) {
        float2 cs = sincos_red(129.0f, sxp[l >> 1][l & 1]);
        srot[l >> 1][l & 1][0] = cs.x;
        srot[l >> 1][l & 1][1] = cs.y;
    }
    __syncthreads();

    for (int l = tid; l < PPTS * (TI + TJ); l += NTHR_T) {
        if (l < PPTS * TI) {
            int pt = l / TI, ii = l - pt * TI;
            int gi = i0 + ii;
            float2 a = make_float2(0.0f, 0.0f);
            if (gi < TROWS)
                a = eval_fast((float)(gi - KOFF), sxp[pt][0], srot[pt][0][0], srot[pt][0][1]);
            sAx[pt][ii] = a.x; sAy[pt][ii] = a.y;
        } else {
            int l2 = l - PPTS * TI;
            int pt = l2 / TJ, jj = l2 - pt * TJ;
            int gj = j0 + jj;
            float2 bb = make_float2(0.0f, 0.0f);
            if (gj < MESH)
                bb = eval_fast((float)(gj - KOFF), sxp[pt][1], srot[pt][1][0], srot[pt][1][1]);
            sBx[pt][jj] = bb.x; sBy[pt][jj] = bb.y;
        }
    }
    __syncthreads();

    u64 accx[2], accy[2];
    u64 Z = pack2(0.0f, 0.0f);
    accx[0] = Z; accx[1] = Z; accy[0] = Z; accy[1] = Z;

    const u64 SGN = 0x8000000080000000ULL;

    #pragma unroll 4
    for (int pp = 0; pp < PPTS; ++pp) {
        float2 bxv = *reinterpret_cast<const float2*>(&sBx[pp][tx * 2]);
        float2 byv = *reinterpret_cast<const float2*>(&sBy[pp][tx * 2]);
        u64 bxb[2] = { pack2(bxv.x, bxv.x), pack2(bxv.y, bxv.y) };
        u64 byb[2] = { pack2(byv.x, byv.x), pack2(byv.y, byv.y) };
        u64 ax2 = *reinterpret_cast<const u64*>(&sAx[pp][ty * 2]);
        u64 ay2 = *reinterpret_cast<const u64*>(&sAy[pp][ty * 2]);
        u64 an2 = ay2 ^ SGN;
        #pragma unroll
        for (int c = 0; c < 2; c++) {
            accx[c] = fma2(ax2, bxb[c], accx[c]);
            accx[c] = fma2(an2, byb[c], accx[c]);
            accy[c] = fma2(ax2, byb[c], accy[c]);
            accy[c] = fma2(ay2, bxb[c], accy[c]);
        }
    }

    float2* Tp = g_Tp + (pc * NB + b) * TN;
    #pragma unroll
    for (int c = 0; c < 2; c++) {
        float v0, v1, w0, w1;
        unpack2(accx[c], v0, v1);
        unpack2(accy[c], w0, w1);
        int gj = j0 + tx * 2 + c;
        int gi = i0 + ty * 2;
        if (gj < MESH) {
            if (gi     < TROWS) Tp[gi       * MESH + gj] = make_float2(v0, w0);
            if (gi + 1 < TROWS) Tp[(gi + 1) * MESH + gj] = make_float2(v1, w1);
        }
    }

    __threadfence();
    int cidx = (b * ITILES + blockIdx.y) * JTILES + blockIdx.x;
    if (tid == 0) s_ticket = atomicAdd(&g_cntT[cidx], 1);
    __syncthreads();
    if (s_ticket == PC - 1) {
        int rows = TROWS - i0; if (rows > TI) rows = TI;
        for (int l = tid; l < rows * TJ; l += NTHR_T) {
            int r = l / TJ, c = l - r * TJ;
            int gi = i0 + r, gj = j0 + c;
            if (gj >= MESH) continue;
            int off = gi * MESH + gj;
            float tsx = 0.0f, tsy = 0.0f;
            #pragma unroll
            for (int p2 = 0; p2 < PC; p2++) {
                float2 v = __ldcg(&g_Tp[(p2 * NB + b) * TN + off]);
                tsx += v.x; tsy += v.y;
            }
            float w0 = 0.0f, w1 = 0.0f;
            if (off < HALF) {
                float kx = (float)(gi - KOFF);
                float ky = (float)(gj - KOFF);
                float k2s = kx * kx + ky * ky;
                constexpr double PI_D  = 3.14159265358979323846;
                constexpr double TAU_D = 12.0 / (129.0 * 129.0);
                constexpr double MD    = 129.0;
                constexpr double PREF_D = (PI_D / TAU_D) * (PI_D / TAU_D) * 4.0 * PI_D
                                        / (MD*MD*MD*MD * (2.0*PI_D) * (2.0*PI_D) * 2.0);
                float f = (off == HALF - 1) ? 1.0f : 2.0f;
                float base = f * (float)PREF_D * expf(2.0f * (float)TAU_D * k2s);
                float sh0 = s0[0], sh1 = s1[0];
                w0 = base * a0[0] / (k2s + sh0 * sh0);
                w1 = base * a1[0] / (k2s + sh1 * sh1);
            }
            g_TW[b * TN + off] = make_float4(tsx, tsy, w0, w1);
        }
        if (tid == 0) g_cntT[cidx] = 0;
    }
}

// ---------------------------------------------------------------------------
// Kernel B: E_c[b,p] = sum over all TN modes (zero weights beyond HALF) of
// W_c * ( Re(conj(S)T) - |S|^2 ).  Balanced sweep:
//   regular: rows 0..63 x cols 0..127, warp w owns rows {w,w+16,w+32,w+48}
//   extras : 193 leftover modes (row 64 + col 128) one-per-thread in parallel
// ---------------------------------------------------------------------------
__global__ void __launch_bounds__(NTHR_E) k_energy(
    const float* __restrict__ x, float* __restrict__ out)
{
    __shared__ __align__(16) float4 sA[TROWS][9];   // [k1][pr] = (ax_lo,ax_hi,ay_lo,ay_hi)
    __shared__ __align__(16) float4 sB2[8][132];    // [pr][k2] = (bx_lo,bx_hi,by_lo,by_hi)
    __shared__ float red[32][16];
    __shared__ float sxp[PTS][2];
    __shared__ float srot[PTS][2][2];

    int b  = blockIdx.y;
    int p0 = blockIdx.x * PTS;
    int tid = threadIdx.x;   // 512
    int lane = tid & 31, warp = tid >> 5;   // 16 warps

    if (tid < PTS * 2)
        sxp[tid >> 1][tid & 1] = x[(b * NP + p0 + (tid >> 1)) * 2 + (tid & 1)];
    __syncthreads();
    if (tid < PTS * 2) {
        float2 cs = sincos_red(129.0f, sxp[tid >> 1][tid & 1]);
        srot[tid >> 1][tid & 1][0] = cs.x;
        srot[tid >> 1][tid & 1][1] = cs.y;
    }
    __syncthreads();

    for (int l = tid; l < PTS * TROWS; l += NTHR_E) {
        int pt = l & (PTS - 1), k = l >> 4;
        float2 a = eval_fast((float)(k - KOFF), sxp[pt][0], srot[pt][0][0], srot[pt][0][1]);
        float* dst = reinterpret_cast<float*>(&sA[k][pt >> 1]);
        dst[pt & 1]       = a.x;
        dst[2 + (pt & 1)] = a.y;
    }
    for (int l = tid; l < PTS * MESH; l += NTHR_E) {
        int pt = l & (PTS - 1), k = l >> 4;
        float2 bb = eval_fast((float)(k - KOFF), sxp[pt][1], srot[pt][1][0], srot[pt][1][1]);
        float* dst = reinterpret_cast<float*>(&sB2[pt >> 1][k]);
        dst[pt & 1]       = bb.x;
        dst[2 + (pt & 1)] = bb.y;
    }
    __syncthreads();

    u64 e0[8], e1[8];
    u64 Zr = pack2(0.0f, 0.0f);
    #pragma unroll
    for (int pr = 0; pr < 8; pr++) { e0[pr] = Zr; e1[pr] = Zr; }
    const u64 NEG1 = pack2(-1.0f, -1.0f);
    const u64 SGN  = 0x8000000080000000ULL;

    const float4* __restrict__ TW = g_TW + b * TN;

    // ---- regular part: rows 0..63, cols 0..127 ----
    #pragma unroll
    for (int rr = 0; rr < 4; rr++) {
        int k1 = warp + 16 * rr;

        u64 ax[8], ay[8];
        const ulonglong2* __restrict__ Arow = reinterpret_cast<const ulonglong2*>(&sA[k1][0]);
        #pragma unroll
        for (int pr = 0; pr < 8; pr++) {
            ulonglong2 av = Arow[pr];
            ax[pr] = av.x; ay[pr] = av.y;
        }

        const float4* __restrict__ TWrow = TW + k1 * MESH;
        float4 tw[4];
        #pragma unroll
        for (int j = 0; j < 4; j++) tw[j] = __ldg(&TWrow[lane + 32 * j]);   // MLP=4, coalesced

        #pragma unroll
        for (int j = 0; j < 4; j++) {
            int k2 = lane + 32 * j;
            u64 tx2 = pack2(tw[j].x, tw[j].x);
            u64 ty2 = pack2(tw[j].y, tw[j].y);
            u64 w02 = pack2(tw[j].z, tw[j].z);
            u64 w12 = pack2(tw[j].w, tw[j].w);
            #pragma unroll
            for (int pr = 0; pr < 8; pr++) {
                ulonglong2 bv = *reinterpret_cast<const ulonglong2*>(&sB2[pr][k2]);
                u64 bx2 = bv.x, by2 = bv.y;
                u64 an2 = ay[pr] ^ SGN;
                u64 sx2 = fma2(ax[pr], bx2, mul2(an2, by2));
                u64 sy2 = fma2(ax[pr], by2, mul2(ay[pr], bx2));
                u64 dx2 = fma2(sx2, NEG1, tx2);
                u64 dy2 = fma2(sy2, NEG1, ty2);
                u64 v2  = fma2(sx2, dx2, mul2(sy2, dy2));
                e0[pr] = fma2(w02, v2, e0[pr]);
                e1[pr] = fma2(w12, v2, e1[pr]);
            }
        }
    }

    // ---- extras: 193 leftover modes, one per thread (parallel across warps) ----
    if (tid < 129 + 64) {
        int k1 = (tid < 129) ? 64 : (tid - 129);
        int k2 = (tid < 129) ? tid : 128;
        float4 twl = __ldg(&TW[k1 * MESH + k2]);
        u64 tx2 = pack2(twl.x, twl.x);
        u64 ty2 = pack2(twl.y, twl.y);
        u64 w02 = pack2(twl.z, twl.z);
        u64 w12 = pack2(twl.w, twl.w);
        const ulonglong2* __restrict__ Arow = reinterpret_cast<const ulonglong2*>(&sA[k1][0]);
        #pragma unroll
        for (int pr = 0; pr < 8; pr++) {
            ulonglong2 av = Arow[pr];
            ulonglong2 bv = *reinterpret_cast<const ulonglong2*>(&sB2[pr][k2]);
            u64 ax2 = av.x, ay2 = av.y;
            u64 bx2 = bv.x, by2 = bv.y;
            u64 an2 = ay2 ^ SGN;
            u64 sx2 = fma2(ax2, bx2, mul2(an2, by2));
            u64 sy2 = fma2(ax2, by2, mul2(ay2, bx2));
            u64 dx2 = fma2(sx2, NEG1, tx2);
            u64 dy2 = fma2(sy2, NEG1, ty2);
            u64 v2  = fma2(sx2, dx2, mul2(sy2, dy2));
            e0[pr] = fma2(w02, v2, e0[pr]);
            e1[pr] = fma2(w12, v2, e1[pr]);
        }
    }

    float ev[32];
    #pragma unroll
    for (int pr = 0; pr < 8; pr++) {
        float a, bq;
        unpack2(e0[pr], a, bq);
        ev[(2 * pr) * 2 + 0] = a;  ev[(2 * pr + 1) * 2 + 0] = bq;
        unpack2(e1[pr], a, bq);
        ev[(2 * pr) * 2 + 1] = a;  ev[(2 * pr + 1) * 2 + 1] = bq;
    }

    #pragma unroll
    for (int v = 0; v < 32; v++) {
        float val = ev[v];
        #pragma unroll
        for (int off = 16; off; off >>= 1)
            val += __shfl_down_sync(0xffffffffu, val, off);
        if (lane == 0) red[v][warp] = val;
    }
    __syncthreads();
    if (tid < 32) {
        float s = 0.0f;
        #pragma unroll
        for (int wq = 0; wq < 16; wq++) s += red[tid][wq];
        int p = tid >> 1, c = tid & 1;
        out[(b * NP + p0 + p) * 2 + c] = s;
    }
}

// ---------------------------------------------------------------------------
extern "C" void kernel_launch(void* const* d_in, const int* in_sizes, int n_in,
                              void* d_out, int out_size)
{
    const float* x  = (const float*)d_in[0];
    const float* s0 = (const float*)d_in[1];
    const float* s1 = (const float*)d_in[2];
    const float* a0 = (const float*)d_in[3];
    const float* a1 = (const float*)d_in[4];

    k_T<<<dim3(JTILES, ITILES, NB * PC), NTHR_T>>>(x, s0, s1, a0, a1);
    k_energy<<<dim3(NP / PTS, NB), NTHR_E>>>(x, (float*)d_out);
}

// round 14
// speedup vs baseline: 1.1242x; 1.1242x over previous
#include <cuda_runtime.h>
#include <math.h>

#define MESH  129
#define NB    4
#define NP    512
#define BP    2048
#define KOFF  64
#define HALF  8321               // modes idx <= center; rest via Hermitian symmetry
#define TROWS 65
#define TN    (TROWS*MESH)       // 8385
#define PC    8                  // p-chunks in k_T
#define PPTS  (NP/PC)            // 64 points per k_T block
#define TI    18                 // k_T i-tile rows
#define TJ    26                 // k_T j-tile cols
#define ITILES 4
#define JTILES 5
#define NTHR_T 117               // 13 x 9
#define PTS   16                 // points per k_energy block (8 packed pairs)
#define NTHR_E 512               // k_energy threads (16 warps, 1 block/SM)

typedef unsigned long long u64;

// ---- f32x2 packed helpers ----
__device__ __forceinline__ u64 fma2(u64 a, u64 b, u64 c) {
    u64 d; asm("fma.rn.f32x2 %0, %1, %2, %3;" : "=l"(d) : "l"(a), "l"(b), "l"(c)); return d;
}
__device__ __forceinline__ u64 mul2(u64 a, u64 b) {
    u64 d; asm("mul.rn.f32x2 %0, %1, %2;" : "=l"(d) : "l"(a), "l"(b)); return d;
}
__device__ __forceinline__ u64 pack2(float lo, float hi) {
    u64 d; asm("mov.b64 %0, {%1, %2};" : "=l"(d) : "r"(__float_as_uint(lo)), "r"(__float_as_uint(hi))); return d;
}
__device__ __forceinline__ void unpack2(u64 v, float& lo, float& hi) {
    unsigned a, b; asm("mov.b64 {%0, %1}, %2;" : "=r"(a), "=r"(b) : "l"(v));
    lo = __uint_as_float(a); hi = __uint_as_float(b);
}

// Scratch (__device__ globals; no allocation allowed)
__device__ float2 g_Tp[PC*NB*TN];
__device__ float4 g_TW[NB*TN];
__device__ int    g_cntT[NB*ITILES*JTILES];

// ---- constants ----
#define TAUF   ((float)(12.0 / (129.0 * 129.0)))
#define T258   (258.0f * TAUF)
#define KC     6.144212353e-6f          /* e^{-129^2 * tau} = e^{-12} */
#define INV2PI 0.15915494309189535f
#define PI2_HI 6.28318548202514648f
#define PI2_LO (-1.74845553e-7f)

// cos/sin of (m*xx) with exact-product + Cody-Waite 2pi reduction
__device__ __forceinline__ float2 sincos_red(float m, float xx)
{
    float ph = m * xx;
    float pl = fmaf(m, xx, -ph);
    float n  = rintf(ph * INV2PI);
    float r  = fmaf(n, -PI2_HI, ph);
    r = fmaf(n, -PI2_LO, r);
    r += pl;
    float s, c;
    __sincosf(r, &s, &c);
    return make_float2(c, s);
}

// Fast closed-form 1D DFT of periodic spread Gaussian.
__device__ __forceinline__ float2 eval_fast(float kk, float xx, float rc, float rs)
{
    const float Cst = 129.0f * sqrtf(12.566370614f * TAUF) * INV2PI;
    float E  = __expf(-TAUF * kk * kk) * Cst;
    float D  = __expf(-T258 * kk);
    float Di = __fdividef(1.0f, D);
    float ep = D * KC, em = Di * KC;
    float2 cs = sincos_red(kk, xx);
    float bc = cs.x, bs = -cs.y;                  // base = e^{-i kk x}
    float tpre = fmaf(bc, rc,  bs * rs);
    float tpim = fmaf(bs, rc, -bc * rs);
    float tmre = fmaf(bc, rc, -bs * rs);
    float tmim = fmaf(bc, rs,  bs * rc);
    float re = fmaf(ep, tpre, fmaf(em, tmre, bc));
    float im = fmaf(ep, tpim, fmaf(em, tmim, bs));
    return make_float2(E * re, E * im);
}

// ---------------------------------------------------------------------------
// Kernel A: partial T[pc,b,i,j] = sum_p A[p,i]*B[p,j]; 18x26 tiles, 117 thr.
// Grid 5x4x32 = 640 blocks (~4.3/SM). Tail block fuses partials + weights.
// PDL: trigger fires after staging so the dependent k_energy can begin
// its own (g_TW-independent) staging while this kernel computes.
// ---------------------------------------------------------------------------
__global__ void __launch_bounds__(NTHR_T) k_T(
    const float* __restrict__ x,
    const float* __restrict__ s0, const float* __restrict__ s1,
    const float* __restrict__ a0, const float* __restrict__ a1)
{
    __shared__ float sAx[PPTS][TI];
    __shared__ float sAy[PPTS][TI];
    __shared__ float sBx[PPTS][TJ];
    __shared__ float sBy[PPTS][TJ];
    __shared__ float sxp[PPTS][2];
    __shared__ float srot[PPTS][2][2];
    __shared__ int s_ticket;

    int b  = blockIdx.z & 3;
    int pc = blockIdx.z >> 2;
    int i0 = blockIdx.y * TI;
    int j0 = blockIdx.x * TJ;
    int tid = threadIdx.x;
    int tx = tid % 13, ty = tid / 13;

    const int pbase = b * NP + pc * PPTS;

    for (int l = tid; l < PPTS * 2; l += NTHR_T)
        sxp[l >> 1][l & 1] = x[(pbase + (l >> 1)) * 2 + (l & 1)];
    __syncthreads();
    for (int l = tid; l < PPTS * 2; l += NTHR_T) {
        float2 cs = sincos_red(129.0f, sxp[l >> 1][l & 1]);
        srot[l >> 1][l & 1][0] = cs.x;
        srot[l >> 1][l & 1][1] = cs.y;
    }
    __syncthreads();

    for (int l = tid; l < PPTS * (TI + TJ); l += NTHR_T) {
        if (l < PPTS * TI) {
            int pt = l / TI, ii = l - pt * TI;
            int gi = i0 + ii;
            float2 a = make_float2(0.0f, 0.0f);
            if (gi < TROWS)
                a = eval_fast((float)(gi - KOFF), sxp[pt][0], srot[pt][0][0], srot[pt][0][1]);
            sAx[pt][ii] = a.x; sAy[pt][ii] = a.y;
        } else {
            int l2 = l - PPTS * TI;
            int pt = l2 / TJ, jj = l2 - pt * TJ;
            int gj = j0 + jj;
            float2 bb = make_float2(0.0f, 0.0f);
            if (gj < MESH)
                bb = eval_fast((float)(gj - KOFF), sxp[pt][1], srot[pt][1][0], srot[pt][1][1]);
            sBx[pt][jj] = bb.x; sBy[pt][jj] = bb.y;
        }
    }
    __syncthreads();

#if __CUDA_ARCH__ >= 900
    cudaTriggerProgrammaticLaunchCompletion();
#endif

    u64 accx[2], accy[2];
    u64 Z = pack2(0.0f, 0.0f);
    accx[0] = Z; accx[1] = Z; accy[0] = Z; accy[1] = Z;

    const u64 SGN = 0x8000000080000000ULL;

    #pragma unroll 4
    for (int pp = 0; pp < PPTS; ++pp) {
        float2 bxv = *reinterpret_cast<const float2*>(&sBx[pp][tx * 2]);
        float2 byv = *reinterpret_cast<const float2*>(&sBy[pp][tx * 2]);
        u64 bxb[2] = { pack2(bxv.x, bxv.x), pack2(bxv.y, bxv.y) };
        u64 byb[2] = { pack2(byv.x, byv.x), pack2(byv.y, byv.y) };
        u64 ax2 = *reinterpret_cast<const u64*>(&sAx[pp][ty * 2]);
        u64 ay2 = *reinterpret_cast<const u64*>(&sAy[pp][ty * 2]);
        u64 an2 = ay2 ^ SGN;
        #pragma unroll
        for (int c = 0; c < 2; c++) {
            accx[c] = fma2(ax2, bxb[c], accx[c]);
            accx[c] = fma2(an2, byb[c], accx[c]);
            accy[c] = fma2(ax2, byb[c], accy[c]);
            accy[c] = fma2(ay2, bxb[c], accy[c]);
        }
    }

    float2* Tp = g_Tp + (pc * NB + b) * TN;
    #pragma unroll
    for (int c = 0; c < 2; c++) {
        float v0, v1, w0, w1;
        unpack2(accx[c], v0, v1);
        unpack2(accy[c], w0, w1);
        int gj = j0 + tx * 2 + c;
        int gi = i0 + ty * 2;
        if (gj < MESH) {
            if (gi     < TROWS) Tp[gi       * MESH + gj] = make_float2(v0, w0);
            if (gi + 1 < TROWS) Tp[(gi + 1) * MESH + gj] = make_float2(v1, w1);
        }
    }

    __threadfence();
    int cidx = (b * ITILES + blockIdx.y) * JTILES + blockIdx.x;
    if (tid == 0) s_ticket = atomicAdd(&g_cntT[cidx], 1);
    __syncthreads();
    if (s_ticket == PC - 1) {
        int rows = TROWS - i0; if (rows > TI) rows = TI;
        for (int l = tid; l < rows * TJ; l += NTHR_T) {
            int r = l / TJ, c = l - r * TJ;
            int gi = i0 + r, gj = j0 + c;
            if (gj >= MESH) continue;
            int off = gi * MESH + gj;
            float tsx = 0.0f, tsy = 0.0f;
            #pragma unroll
            for (int p2 = 0; p2 < PC; p2++) {
                float2 v = __ldcg(&g_Tp[(p2 * NB + b) * TN + off]);
                tsx += v.x; tsy += v.y;
            }
            float w0 = 0.0f, w1 = 0.0f;
            if (off < HALF) {
                float kx = (float)(gi - KOFF);
                float ky = (float)(gj - KOFF);
                float k2s = kx * kx + ky * ky;
                constexpr double PI_D  = 3.14159265358979323846;
                constexpr double TAU_D = 12.0 / (129.0 * 129.0);
                constexpr double MD    = 129.0;
                constexpr double PREF_D = (PI_D / TAU_D) * (PI_D / TAU_D) * 4.0 * PI_D
                                        / (MD*MD*MD*MD * (2.0*PI_D) * (2.0*PI_D) * 2.0);
                float f = (off == HALF - 1) ? 1.0f : 2.0f;
                float base = f * (float)PREF_D * expf(2.0f * (float)TAU_D * k2s);
                float sh0 = s0[0], sh1 = s1[0];
                w0 = base * a0[0] / (k2s + sh0 * sh0);
                w1 = base * a1[0] / (k2s + sh1 * sh1);
            }
            g_TW[b * TN + off] = make_float4(tsx, tsy, w0, w1);
        }
        if (tid == 0) g_cntT[cidx] = 0;
    }
}

// ---------------------------------------------------------------------------
// Kernel B: E_c[b,p] = sum_{idx<HALF} W_c * ( Re(conj(S)T) - |S|^2 ).
// 512 threads, grid 32x4 = 128 blocks (1/SM, single wave, 4 warps/SMSP).
// Stages its S-factor tables (independent of g_TW) BEFORE the PDL grid
// dependency sync, overlapping with k_T's mainloop.
// ---------------------------------------------------------------------------
__global__ void __launch_bounds__(NTHR_E) k_energy(
    const float* __restrict__ x, float* __restrict__ out)
{
    __shared__ __align__(16) float4 sA[TROWS][9];   // [k1][pr] = (ax_lo,ax_hi,ay_lo,ay_hi)
    __shared__ __align__(16) float4 sB[MESH][9];    // [k2][pr] = (bx_lo,bx_hi,by_lo,by_hi)
    __shared__ float red[32][16];
    __shared__ float sxp[PTS][2];
    __shared__ float srot[PTS][2][2];

    int b  = blockIdx.y;
    int p0 = blockIdx.x * PTS;
    int tid = threadIdx.x;   // 512

    if (tid < PTS * 2)
        sxp[tid >> 1][tid & 1] = x[(b * NP + p0 + (tid >> 1)) * 2 + (tid & 1)];
    __syncthreads();
    if (tid < PTS * 2) {
        float2 cs = sincos_red(129.0f, sxp[tid >> 1][tid & 1]);
        srot[tid >> 1][tid & 1][0] = cs.x;
        srot[tid >> 1][tid & 1][1] = cs.y;
    }
    __syncthreads();

    for (int l = tid; l < PTS * TROWS; l += NTHR_E) {
        int pt = l & (PTS - 1), k = l >> 4;
        float2 a = eval_fast((float)(k - KOFF), sxp[pt][0], srot[pt][0][0], srot[pt][0][1]);
        float* dst = reinterpret_cast<float*>(&sA[k][pt >> 1]);
        dst[pt & 1]       = a.x;
        dst[2 + (pt & 1)] = a.y;
    }
    for (int l = tid; l < PTS * MESH; l += NTHR_E) {
        int pt = l & (PTS - 1), k = l >> 4;
        float2 bb = eval_fast((float)(k - KOFF), sxp[pt][1], srot[pt][1][0], srot[pt][1][1]);
        float* dst = reinterpret_cast<float*>(&sB[k][pt >> 1]);
        dst[pt & 1]       = bb.x;
        dst[2 + (pt & 1)] = bb.y;
    }
    __syncthreads();

#if __CUDA_ARCH__ >= 900
    cudaGridDependencySynchronize();   // wait for k_T's g_TW writes
#endif

    u64 e0[8], e1[8];
    u64 Zr = pack2(0.0f, 0.0f);
    #pragma unroll
    for (int pr = 0; pr < 8; pr++) { e0[pr] = Zr; e1[pr] = Zr; }
    const u64 NEG1 = pack2(-1.0f, -1.0f);
    const u64 SGN  = 0x8000000080000000ULL;

    const float4* __restrict__ TW = g_TW + b * TN;

    int idx = tid;
    int k1 = idx / MESH;
    int k2 = idx - k1 * MESH;
    float4 tw = __ldg(&TW[idx]);                 // prologue load
    while (idx < HALF) {
        int nidx = idx + NTHR_E;
        int cidx2 = (nidx < HALF) ? nidx : idx;  // clamped prefetch index
        float4 twn = __ldg(&TW[cidx2]);          // prefetch next iteration

        u64 tx2 = pack2(tw.x, tw.x);
        u64 ty2 = pack2(tw.y, tw.y);
        u64 w02 = pack2(tw.z, tw.z);
        u64 w12 = pack2(tw.w, tw.w);
        const ulonglong2* __restrict__ Arow = reinterpret_cast<const ulonglong2*>(&sA[k1][0]);
        const ulonglong2* __restrict__ Brow = reinterpret_cast<const ulonglong2*>(&sB[k2][0]);
        #pragma unroll
        for (int pr = 0; pr < 8; pr++) {
            ulonglong2 av = Arow[pr];       // LDS.128 (broadcast across warp)
            ulonglong2 bv = Brow[pr];       // LDS.128 (conflict-free, pad=9)
            u64 ax2 = av.x, ay2 = av.y;
            u64 bx2 = bv.x, by2 = bv.y;
            u64 an2 = ay2 ^ SGN;
            u64 sx2 = fma2(ax2, bx2, mul2(an2, by2));
            u64 sy2 = fma2(ax2, by2, mul2(ay2, bx2));
            u64 dx2 = fma2(sx2, NEG1, tx2);
            u64 dy2 = fma2(sy2, NEG1, ty2);
            u64 v2  = fma2(sx2, dx2, mul2(sy2, dy2));
            e0[pr] = fma2(w02, v2, e0[pr]);
            e1[pr] = fma2(w12, v2, e1[pr]);
        }
        tw = twn;
        idx = nidx;
        // incremental (k1,k2) update: stride 512 = 3*129 + 125
        k1 += 3; k2 += 125;
        if (k2 >= MESH) { k2 -= MESH; k1 += 1; }
    }

    float ev[32];
    #pragma unroll
    for (int pr = 0; pr < 8; pr++) {
        float a, bq;
        unpack2(e0[pr], a, bq);
        ev[(2 * pr) * 2 + 0] = a;  ev[(2 * pr + 1) * 2 + 0] = bq;
        unpack2(e1[pr], a, bq);
        ev[(2 * pr) * 2 + 1] = a;  ev[(2 * pr + 1) * 2 + 1] = bq;
    }

    int lane = tid & 31, warp = tid >> 5;   // 16 warps
    #pragma unroll
    for (int v = 0; v < 32; v++) {
        float val = ev[v];
        #pragma unroll
        for (int off = 16; off; off >>= 1)
            val += __shfl_down_sync(0xffffffffu, val, off);
        if (lane == 0) red[v][warp] = val;
    }
    __syncthreads();
    if (tid < 32) {
        float s = 0.0f;
        #pragma unroll
        for (int wq = 0; wq < 16; wq++) s += red[tid][wq];
        int p = tid >> 1, c = tid & 1;
        out[(b * NP + p0 + p) * 2 + c] = s;
    }
}

// ---------------------------------------------------------------------------
extern "C" void kernel_launch(void* const* d_in, const int* in_sizes, int n_in,
                              void* d_out, int out_size)
{
    const float* x  = (const float*)d_in[0];
    const float* s0 = (const float*)d_in[1];
    const float* s1 = (const float*)d_in[2];
    const float* a0 = (const float*)d_in[3];
    const float* a1 = (const float*)d_in[4];

    k_T<<<dim3(JTILES, ITILES, NB * PC), NTHR_T>>>(x, s0, s1, a0, a1);

    // Programmatic dependent launch: k_energy may start early (its staging
    // is g_TW-independent); it grid-dep-syncs before touching g_TW.
    cudaLaunchConfig_t cfg = {};
    cfg.gridDim  = dim3(NP / PTS, NB);
    cfg.blockDim = dim3(NTHR_E);
    cfg.dynamicSmemBytes = 0;
    cfg.stream = 0;
    cudaLaunchAttribute attrs[1];
    attrs[0].id = cudaLaunchAttributeProgrammaticStreamSerialization;
    attrs[0].val.programmaticStreamSerializationAllowed = 1;
    cfg.attrs = attrs;
    cfg.numAttrs = 1;
    cudaLaunchKernelEx(&cfg, k_energy, x, (float*)d_out);
}